// round 13
// baseline (speedup 1.0000x reference)
#include <cuda_runtime.h>
#include <cstdint>

// MeanAggregatorHead: out[b,:] = (1/K) * sum_k tab[idx[b,k],:]
// B=100000, K=32, N=500000, D=128, fp32 table, int32 indices.
//
// R13: smem-resident accumulators (min L2 bytes: 1.70GB) with the R11/R12
// latency chains removed: indices register-resident across phases, idx
// loads batched ahead of the ballot sort, accumulator prefetched before
// each gather, all node loops fully unrolled so ptxas interleaves
// independent nodes' LDGs. 6 CTAs/SM pinned via launch_bounds.

constexpr int K       = 32;
constexpr int D       = 128;
constexpr int THREADS = 256;      // 8 warps
constexpr int NPW     = 5;        // nodes per warp (register arrays sized this)
constexpr int NPC     = NPW * 8;  // 40 nodes per CTA -> grid 2500 exactly
constexpr int PHASES  = 4;

// Dense gather over slots [start, end): 4-wide LDG.128 batching (R8/R10).
__device__ __forceinline__ float4 dense_gather(
    const float* __restrict__ tab, int v, int lane, int start, int end)
{
    float4 acc = make_float4(0.f, 0.f, 0.f, 0.f);
    int j = start;
    #pragma unroll 1
    for (; j + 4 <= end; j += 4) {
        int r0 = __shfl_sync(0xffffffffu, v, j);
        int r1 = __shfl_sync(0xffffffffu, v, j + 1);
        int r2 = __shfl_sync(0xffffffffu, v, j + 2);
        int r3 = __shfl_sync(0xffffffffu, v, j + 3);
        float4 a0 = __ldg(&reinterpret_cast<const float4*>(tab + (size_t)r0 * D)[lane]);
        float4 a1 = __ldg(&reinterpret_cast<const float4*>(tab + (size_t)r1 * D)[lane]);
        float4 a2 = __ldg(&reinterpret_cast<const float4*>(tab + (size_t)r2 * D)[lane]);
        float4 a3 = __ldg(&reinterpret_cast<const float4*>(tab + (size_t)r3 * D)[lane]);
        acc.x += (a0.x + a1.x) + (a2.x + a3.x);
        acc.y += (a0.y + a1.y) + (a2.y + a3.y);
        acc.z += (a0.z + a1.z) + (a2.z + a3.z);
        acc.w += (a0.w + a1.w) + (a2.w + a3.w);
    }
    #pragma unroll 1
    for (; j < end; ++j) {
        int r = __shfl_sync(0xffffffffu, v, j);
        float4 a = __ldg(&reinterpret_cast<const float4*>(tab + (size_t)r * D)[lane]);
        acc.x += a.x; acc.y += a.y; acc.z += a.z; acc.w += a.w;
    }
    return acc;
}

__global__ __launch_bounds__(THREADS, 6) void mean_agg_r13(
    const float* __restrict__ tab,
    const int*   __restrict__ idx,
    float* __restrict__ out,
    int B, int c1, int c2, int c3)
{
    __shared__ float4 sacc [NPC * 32];   // 20,480 B  node accumulators
    __shared__ int    sidx [NPC * 32];   //  5,120 B  bucket-reordered indices
    __shared__ int    scnt [NPC];        //    160 B  packed bucket counts

    int tid  = threadIdx.x;
    int w    = tid >> 5;
    int lane = tid & 31;
    int ln0  = w * NPW;                          // warp-exclusive local nodes
    int ctaBase = blockIdx.x * NPC;

    // ---- Phase 0a: batched idx loads (5 independent LDGs in flight) ----
    int r[NPW];
    #pragma unroll
    for (int i = 0; i < NPW; ++i) {
        int gn = min(ctaBase + ln0 + i, B - 1);  // clamp: dup warps write
        r[i] = __ldg(&idx[(size_t)gn * K + lane]); //       identical bytes
    }

    // ---- Phase 0b: ballot bucket-sort each node, indices -> registers ---
    int v[NPW];
    #pragma unroll
    for (int i = 0; i < NPW; ++i) {
        int ln = ln0 + i;
        int b = (r[i] >= c1) + (r[i] >= c2) + (r[i] >= c3);
        unsigned m0 = __ballot_sync(0xffffffffu, b == 0);
        unsigned m1 = __ballot_sync(0xffffffffu, b == 1);
        unsigned m2 = __ballot_sync(0xffffffffu, b == 2);
        unsigned m3 = __ballot_sync(0xffffffffu, b == 3);
        int n0 = __popc(m0), n1 = __popc(m1), n2 = __popc(m2);
        unsigned lt = (1u << lane) - 1u;
        int slot;
        if      (b == 0) slot = __popc(m0 & lt);
        else if (b == 1) slot = n0 + __popc(m1 & lt);
        else if (b == 2) slot = n0 + n1 + __popc(m2 & lt);
        else             slot = n0 + n1 + n2 + __popc(m3 & lt);
        sidx[ln * 32 + slot] = r[i];
        if (lane == 0) scnt[ln] = n0 | (n1 << 8) | (n2 << 16);
        __syncwarp();
        v[i] = sidx[ln * 32 + lane];             // register-resident from here
    }

    // ---- Phase 0c: gather bucket 0, initialize accumulators -------------
    #pragma unroll
    for (int i = 0; i < NPW; ++i) {
        int ln = ln0 + i;
        int n0 = scnt[ln] & 0xff;                // broadcast LDS
        float4 a = dense_gather(tab, v[i], lane, 0, n0);
        sacc[ln * 32 + lane] = a;                // first write, no RMW
    }

    // ---- Phases 1..3: prefetch acc, gather bucket p, add, store ---------
    #pragma unroll
    for (int p = 1; p < PHASES; ++p) {
        #pragma unroll
        for (int i = 0; i < NPW; ++i) {
            int ln = ln0 + i;
            int packed = scnt[ln];               // broadcast LDS, issued early
            float4 c = sacc[ln * 32 + lane];     // prefetch BEFORE gather
            int n0 =  packed        & 0xff;
            int n1 = (packed >> 8)  & 0xff;
            int n2 = (packed >> 16) & 0xff;
            int start, end;
            if      (p == 1) { start = n0;           end = n0 + n1; }
            else if (p == 2) { start = n0 + n1;      end = n0 + n1 + n2; }
            else             { start = n0 + n1 + n2; end = K; }

            float4 a = dense_gather(tab, v[i], lane, start, end);
            c.x += a.x; c.y += a.y; c.z += a.z; c.w += a.w;
            sacc[ln * 32 + lane] = c;
        }
    }

    // ---- Epilogue: scale + store -----------------------------------------
    const float s = 1.0f / (float)K;
    #pragma unroll
    for (int i = 0; i < NPW; ++i) {
        int ln = ln0 + i;
        int gn = min(ctaBase + ln, B - 1);       // dup writes are identical
        float4 a = sacc[ln * 32 + lane];
        a.x *= s; a.y *= s; a.z *= s; a.w *= s;
        reinterpret_cast<float4*>(out + (size_t)gn * D)[lane] = a;
    }
}

extern "C" void kernel_launch(void* const* d_in, const int* in_sizes, int n_in,
                              void* d_out, int out_size)
{
    // Identify inputs by element count (robust to metadata ordering):
    // embed_table: 64,000,000 ; neigh_idx: 3,200,000 ; num_sample: 1
    long long max_sz = -1, mid_sz = -1;
    int ti = 0, ii = 1;
    for (int i = 0; i < n_in; ++i)
        if (in_sizes[i] > max_sz) { max_sz = in_sizes[i]; ti = i; }
    for (int i = 0; i < n_in; ++i)
        if (i != ti && in_sizes[i] > mid_sz) { mid_sz = in_sizes[i]; ii = i; }

    const float* tab = (const float*)d_in[ti];
    const int*   idx = (const int*)d_in[ii];
    float*       out = (float*)d_out;

    int B = out_size / D;                    // 100000
    int N = (int)(max_sz / D);               // 500000 table rows
    int chunk = (N + PHASES - 1) / PHASES;   // 125000 rows = 64MB

    static bool attr_set = false;
    if (!attr_set) {
        cudaFuncSetAttribute(mean_agg_r13,
                             cudaFuncAttributePreferredSharedMemoryCarveout, 100);
        attr_set = true;
    }

    int grid = (B + NPC - 1) / NPC;          // 2500 CTAs (40 nodes each)
    mean_agg_r13<<<grid, THREADS>>>(tab, idx, out, B,
                                    chunk, 2 * chunk, 3 * chunk);
}

// round 14
// speedup vs baseline: 1.3275x; 1.3275x over previous
#include <cuda_runtime.h>
#include <cstdint>

// MeanAggregatorHead: out[b,:] = (1/K) * sum_k tab[idx[b,k],:]
// B=100000, K=32, N=500000, D=128, fp32 table, int32 indices.
//
// R14 = R10 with P=3 (85MB chunks). Kernel-per-pass is load-bearing: the
// launch boundary is the grid-wide sync that keeps each chunk L2-resident.
// Every pass runs at the ~12.7TB/s LTS cap, so time = L2 bytes / cap.
// P=3 deletes one pass of plumbing (51MB red.add + 12.8MB sidx re-read +
// launch tail) vs P=4: ~1.85GB total -> ~146us.

constexpr int K       = 32;
constexpr int D       = 128;
constexpr int PASSES  = 3;
constexpr int MAX_B   = 100000;
constexpr int WPB     = 8;          // warps per block (256 threads)

__device__ int g_sidx[MAX_B * K];   // bucket-reordered indices (12.8MB)
__device__ int g_cnt [MAX_B];       // packed counts c0|c1<<8 (0.4MB)

__device__ __forceinline__ void red_add_f4(float4* p, float4 v) {
    asm volatile("red.global.add.v4.f32 [%0], {%1,%2,%3,%4};"
                 :: "l"(p), "f"(v.x), "f"(v.y), "f"(v.z), "f"(v.w) : "memory");
}

// Dense gather over slots [start, end) of warp-held reordered index v.
// 4-wide batching: 4 independent LDG.128 per iteration, regs stay ~32.
__device__ __forceinline__ float4 dense_gather(
    const float* __restrict__ tab, int v, int lane, int start, int end)
{
    float4 acc = make_float4(0.f, 0.f, 0.f, 0.f);
    int j = start;
    #pragma unroll 1
    for (; j + 4 <= end; j += 4) {
        int r0 = __shfl_sync(0xffffffffu, v, j);
        int r1 = __shfl_sync(0xffffffffu, v, j + 1);
        int r2 = __shfl_sync(0xffffffffu, v, j + 2);
        int r3 = __shfl_sync(0xffffffffu, v, j + 3);
        float4 a0 = __ldg(&reinterpret_cast<const float4*>(tab + (size_t)r0 * D)[lane]);
        float4 a1 = __ldg(&reinterpret_cast<const float4*>(tab + (size_t)r1 * D)[lane]);
        float4 a2 = __ldg(&reinterpret_cast<const float4*>(tab + (size_t)r2 * D)[lane]);
        float4 a3 = __ldg(&reinterpret_cast<const float4*>(tab + (size_t)r3 * D)[lane]);
        acc.x += (a0.x + a1.x) + (a2.x + a3.x);
        acc.y += (a0.y + a1.y) + (a2.y + a3.y);
        acc.z += (a0.z + a1.z) + (a2.z + a3.z);
        acc.w += (a0.w + a1.w) + (a2.w + a3.w);
    }
    #pragma unroll 1
    for (; j < end; ++j) {
        int r = __shfl_sync(0xffffffffu, v, j);
        float4 a = __ldg(&reinterpret_cast<const float4*>(tab + (size_t)r * D)[lane]);
        acc.x += a.x; acc.y += a.y; acc.z += a.z; acc.w += a.w;
    }
    return acc;
}

// Pass 0: partition (3 buckets) + gather bucket 0, fused.
__global__ __launch_bounds__(WPB * 32) void partition_pass0(
    const float* __restrict__ tab,
    const int*   __restrict__ idx,
    float* __restrict__ out,
    int B, int c1, int c2)
{
    __shared__ int stage[WPB * 32];
    int tid  = threadIdx.x;
    int lane = tid & 31;
    int node = blockIdx.x * WPB + (tid >> 5);
    if (node >= B) return;

    int r = __ldg(&idx[(size_t)node * K + lane]);
    int b = (r >= c1) + (r >= c2);                      // bucket 0..2

    unsigned m0 = __ballot_sync(0xffffffffu, b == 0);
    unsigned m1 = __ballot_sync(0xffffffffu, b == 1);
    unsigned m2 = __ballot_sync(0xffffffffu, b == 2);
    int n0 = __popc(m0), n1 = __popc(m1);

    unsigned lt = (1u << lane) - 1u;
    int slot;
    if      (b == 0) slot = __popc(m0 & lt);
    else if (b == 1) slot = n0 + __popc(m1 & lt);
    else             slot = n0 + n1 + __popc(m2 & lt);

    int* sw = &stage[(tid >> 5) << 5];
    sw[slot] = r;
    __syncwarp();
    int v = sw[lane];                                   // reordered index

    g_sidx[(size_t)node * K + lane] = v;                // for passes 1-2
    if (lane == 0) g_cnt[node] = n0 | (n1 << 8);

    float4 acc = dense_gather(tab, v, lane, 0, n0);     // bucket 0

    const float s = 1.0f / (float)K;
    acc.x *= s; acc.y *= s; acc.z *= s; acc.w *= s;
    reinterpret_cast<float4*>(out + (size_t)node * D)[lane] = acc;
}

// Passes 1-2: dense gather over one bucket, red.add into out.
template <int PASS>
__global__ __launch_bounds__(WPB * 32) void gather_pass(
    const float* __restrict__ tab, float* __restrict__ out, int B)
{
    int tid  = threadIdx.x;
    int lane = tid & 31;
    int node = blockIdx.x * WPB + (tid >> 5);
    if (node >= B) return;

    int v = g_sidx[(size_t)node * K + lane];
    int packed = g_cnt[node];
    int n0 =  packed       & 0xff;
    int n1 = (packed >> 8) & 0xff;

    int start, end;
    if (PASS == 1) { start = n0;      end = n0 + n1; }
    else           { start = n0 + n1; end = K; }

    float4 acc = dense_gather(tab, v, lane, start, end);

    const float s = 1.0f / (float)K;
    acc.x *= s; acc.y *= s; acc.z *= s; acc.w *= s;
    // Single writer per element; passes are stream-ordered -> deterministic.
    red_add_f4(&reinterpret_cast<float4*>(out + (size_t)node * D)[lane], acc);
}

extern "C" void kernel_launch(void* const* d_in, const int* in_sizes, int n_in,
                              void* d_out, int out_size)
{
    // Identify inputs by element count (robust to metadata ordering):
    // embed_table: 64,000,000 ; neigh_idx: 3,200,000 ; num_sample: 1
    long long max_sz = -1, mid_sz = -1;
    int ti = 0, ii = 1;
    for (int i = 0; i < n_in; ++i)
        if (in_sizes[i] > max_sz) { max_sz = in_sizes[i]; ti = i; }
    for (int i = 0; i < n_in; ++i)
        if (i != ti && in_sizes[i] > mid_sz) { mid_sz = in_sizes[i]; ii = i; }

    const float* tab = (const float*)d_in[ti];
    const int*   idx = (const int*)d_in[ii];
    float*       out = (float*)d_out;

    int B = out_size / D;                    // 100000
    int N = (int)(max_sz / D);               // 500000 table rows
    int chunk = (N + PASSES - 1) / PASSES;   // 166667 rows ~ 85MB

    int blocks = (B + WPB - 1) / WPB;        // 12500

    partition_pass0<<<blocks, WPB * 32>>>(tab, idx, out, B, chunk, 2 * chunk);
    gather_pass<1><<<blocks, WPB * 32>>>(tab, out, B);
    gather_pass<2><<<blocks, WPB * 32>>>(tab, out, B);
}

// round 15
// speedup vs baseline: 1.3442x; 1.0126x over previous
#include <cuda_runtime.h>
#include <cstdint>

// MeanAggregatorHead: out[b,:] = (1/K) * sum_k tab[idx[b,k],:]
// B=100000, K=32, N=500000, D=128, fp32 table, int32 indices.
//
// R15 = R14 (P=3 kernel-per-pass, each pass at the ~12.7TB/s LTS cap)
// minus ALL global index scratch: each pass re-loads raw idx (same bytes
// the sidx re-read cost), re-runs the 3-way ballot partition (~40 ALU ops,
// issue headroom is ample), stages via warp smem, and dense-gathers its
// bucket. Deletes g_sidx write (12.8MB) + g_cnt streams. Total L2 ~1.83GB.
// time = L2_bytes / cap; floor for this family = 1.70GB -> 134us.

constexpr int K       = 32;
constexpr int D       = 128;
constexpr int PASSES  = 3;
constexpr int WPB     = 8;          // warps per block (256 threads)

__device__ __forceinline__ void red_add_f4(float4* p, float4 v) {
    asm volatile("red.global.add.v4.f32 [%0], {%1,%2,%3,%4};"
                 :: "l"(p), "f"(v.x), "f"(v.y), "f"(v.z), "f"(v.w) : "memory");
}

// Dense gather over slots [start, end) of warp-held reordered index v.
// 4-wide batching: 4 independent LDG.128 per iteration, regs stay ~32.
__device__ __forceinline__ float4 dense_gather(
    const float* __restrict__ tab, int v, int lane, int start, int end)
{
    float4 acc = make_float4(0.f, 0.f, 0.f, 0.f);
    int j = start;
    #pragma unroll 1
    for (; j + 4 <= end; j += 4) {
        int r0 = __shfl_sync(0xffffffffu, v, j);
        int r1 = __shfl_sync(0xffffffffu, v, j + 1);
        int r2 = __shfl_sync(0xffffffffu, v, j + 2);
        int r3 = __shfl_sync(0xffffffffu, v, j + 3);
        float4 a0 = __ldg(&reinterpret_cast<const float4*>(tab + (size_t)r0 * D)[lane]);
        float4 a1 = __ldg(&reinterpret_cast<const float4*>(tab + (size_t)r1 * D)[lane]);
        float4 a2 = __ldg(&reinterpret_cast<const float4*>(tab + (size_t)r2 * D)[lane]);
        float4 a3 = __ldg(&reinterpret_cast<const float4*>(tab + (size_t)r3 * D)[lane]);
        acc.x += (a0.x + a1.x) + (a2.x + a3.x);
        acc.y += (a0.y + a1.y) + (a2.y + a3.y);
        acc.z += (a0.z + a1.z) + (a2.z + a3.z);
        acc.w += (a0.w + a1.w) + (a2.w + a3.w);
    }
    #pragma unroll 1
    for (; j < end; ++j) {
        int r = __shfl_sync(0xffffffffu, v, j);
        float4 a = __ldg(&reinterpret_cast<const float4*>(tab + (size_t)r * D)[lane]);
        acc.x += a.x; acc.y += a.y; acc.z += a.z; acc.w += a.w;
    }
    return acc;
}

// One pass: load raw idx, ballot-partition into 3 buckets, gather bucket
// PASS densely. PASS 0 stores the scaled partial; PASS 1-2 red.add theirs.
template <int PASS>
__global__ __launch_bounds__(WPB * 32) void agg_pass(
    const float* __restrict__ tab,
    const int*   __restrict__ idx,
    float* __restrict__ out,
    int B, int c1, int c2)
{
    __shared__ int stage[WPB * 32];
    int tid  = threadIdx.x;
    int lane = tid & 31;
    int node = blockIdx.x * WPB + (tid >> 5);
    if (node >= B) return;

    int r = __ldg(&idx[(size_t)node * K + lane]);
    int b = (r >= c1) + (r >= c2);                      // bucket 0..2

    unsigned m0 = __ballot_sync(0xffffffffu, b == 0);
    unsigned m1 = __ballot_sync(0xffffffffu, b == 1);
    unsigned m2 = __ballot_sync(0xffffffffu, b == 2);
    int n0 = __popc(m0), n1 = __popc(m1);

    unsigned lt = (1u << lane) - 1u;
    int slot;
    if      (b == 0) slot = __popc(m0 & lt);
    else if (b == 1) slot = n0 + __popc(m1 & lt);
    else             slot = n0 + n1 + __popc(m2 & lt);

    int* sw = &stage[(tid >> 5) << 5];
    sw[slot] = r;
    __syncwarp();
    int v = sw[lane];                                   // reordered index

    int start, end;
    if      (PASS == 0) { start = 0;       end = n0; }
    else if (PASS == 1) { start = n0;      end = n0 + n1; }
    else                { start = n0 + n1; end = K; }

    float4 acc = dense_gather(tab, v, lane, start, end);

    const float s = 1.0f / (float)K;
    acc.x *= s; acc.y *= s; acc.z *= s; acc.w *= s;

    float4* op = &reinterpret_cast<float4*>(out + (size_t)node * D)[lane];
    if (PASS == 0) *op = acc;             // overwrite (graph-replay safe)
    else           red_add_f4(op, acc);   // ordered passes -> deterministic
}

extern "C" void kernel_launch(void* const* d_in, const int* in_sizes, int n_in,
                              void* d_out, int out_size)
{
    // Identify inputs by element count (robust to metadata ordering):
    // embed_table: 64,000,000 ; neigh_idx: 3,200,000 ; num_sample: 1
    long long max_sz = -1, mid_sz = -1;
    int ti = 0, ii = 1;
    for (int i = 0; i < n_in; ++i)
        if (in_sizes[i] > max_sz) { max_sz = in_sizes[i]; ti = i; }
    for (int i = 0; i < n_in; ++i)
        if (i != ti && in_sizes[i] > mid_sz) { mid_sz = in_sizes[i]; ii = i; }

    const float* tab = (const float*)d_in[ti];
    const int*   idx = (const int*)d_in[ii];
    float*       out = (float*)d_out;

    int B = out_size / D;                    // 100000
    int N = (int)(max_sz / D);               // 500000 table rows
    int chunk = (N + PASSES - 1) / PASSES;   // 166667 rows ~ 85MB

    int blocks = (B + WPB - 1) / WPB;        // 12500

    agg_pass<0><<<blocks, WPB * 32>>>(tab, idx, out, B, chunk, 2 * chunk);
    agg_pass<1><<<blocks, WPB * 32>>>(tab, idx, out, B, chunk, 2 * chunk);
    agg_pass<2><<<blocks, WPB * 32>>>(tab, idx, out, B, chunk, 2 * chunk);
}

// round 16
// speedup vs baseline: 1.4096x; 1.0487x over previous
#include <cuda_runtime.h>
#include <cstdint>

// MeanAggregatorHead: out[b,:] = (1/K) * sum_k tab[idx[b,k],:]
// B=100000, K=32, N=500000, D=128, fp32 table, int32 indices.
//
// R16 = R15 (P=3 kernel-per-pass at the ~12.7TB/s LTS cap; recomputed
// ballot partition; red.add partials) + PDL: each pass triggers
// programmatic launch completion after its gather, and the next pass
// grid-dependency-syncs only before touching out. The next pass's
// idx load + ballot + gather prologue overlaps the prior pass's
// store-drain tail, recovering the pass-boundary serialization cost.

constexpr int K       = 32;
constexpr int D       = 128;
constexpr int PASSES  = 3;
constexpr int WPB     = 8;          // warps per block (256 threads)

__device__ __forceinline__ void red_add_f4(float4* p, float4 v) {
    asm volatile("red.global.add.v4.f32 [%0], {%1,%2,%3,%4};"
                 :: "l"(p), "f"(v.x), "f"(v.y), "f"(v.z), "f"(v.w) : "memory");
}

// Dense gather over slots [start, end) of warp-held reordered index v.
// 4-wide batching: 4 independent LDG.128 per iteration, regs stay ~32.
__device__ __forceinline__ float4 dense_gather(
    const float* __restrict__ tab, int v, int lane, int start, int end)
{
    float4 acc = make_float4(0.f, 0.f, 0.f, 0.f);
    int j = start;
    #pragma unroll 1
    for (; j + 4 <= end; j += 4) {
        int r0 = __shfl_sync(0xffffffffu, v, j);
        int r1 = __shfl_sync(0xffffffffu, v, j + 1);
        int r2 = __shfl_sync(0xffffffffu, v, j + 2);
        int r3 = __shfl_sync(0xffffffffu, v, j + 3);
        float4 a0 = __ldg(&reinterpret_cast<const float4*>(tab + (size_t)r0 * D)[lane]);
        float4 a1 = __ldg(&reinterpret_cast<const float4*>(tab + (size_t)r1 * D)[lane]);
        float4 a2 = __ldg(&reinterpret_cast<const float4*>(tab + (size_t)r2 * D)[lane]);
        float4 a3 = __ldg(&reinterpret_cast<const float4*>(tab + (size_t)r3 * D)[lane]);
        acc.x += (a0.x + a1.x) + (a2.x + a3.x);
        acc.y += (a0.y + a1.y) + (a2.y + a3.y);
        acc.z += (a0.z + a1.z) + (a2.z + a3.z);
        acc.w += (a0.w + a1.w) + (a2.w + a3.w);
    }
    #pragma unroll 1
    for (; j < end; ++j) {
        int r = __shfl_sync(0xffffffffu, v, j);
        float4 a = __ldg(&reinterpret_cast<const float4*>(tab + (size_t)r * D)[lane]);
        acc.x += a.x; acc.y += a.y; acc.z += a.z; acc.w += a.w;
    }
    return acc;
}

// One pass: load raw idx, ballot-partition into 3 buckets, gather bucket
// PASS densely. PASS 0 stores the scaled partial; PASS 1-2 red.add theirs.
// Prologue (idx/tab reads only) runs before the grid dependency sync, so
// it may overlap the tail of the previous pass under PDL.
template <int PASS>
__global__ __launch_bounds__(WPB * 32) void agg_pass(
    const float* __restrict__ tab,
    const int*   __restrict__ idx,
    float* __restrict__ out,
    int B, int c1, int c2)
{
    __shared__ int stage[WPB * 32];
    int tid  = threadIdx.x;
    int lane = tid & 31;
    int node = blockIdx.x * WPB + (tid >> 5);

    float4 acc = make_float4(0.f, 0.f, 0.f, 0.f);
    float4* op = nullptr;

    if (node < B) {
        int r = __ldg(&idx[(size_t)node * K + lane]);
        int b = (r >= c1) + (r >= c2);                  // bucket 0..2

        unsigned m0 = __ballot_sync(0xffffffffu, b == 0);
        unsigned m1 = __ballot_sync(0xffffffffu, b == 1);
        unsigned m2 = __ballot_sync(0xffffffffu, b == 2);
        int n0 = __popc(m0), n1 = __popc(m1);

        unsigned lt = (1u << lane) - 1u;
        int slot;
        if      (b == 0) slot = __popc(m0 & lt);
        else if (b == 1) slot = n0 + __popc(m1 & lt);
        else             slot = n0 + n1 + __popc(m2 & lt);

        int* sw = &stage[(tid >> 5) << 5];
        sw[slot] = r;
        __syncwarp();
        int v = sw[lane];                               // reordered index

        int start, end;
        if      (PASS == 0) { start = 0;       end = n0; }
        else if (PASS == 1) { start = n0;      end = n0 + n1; }
        else                { start = n0 + n1; end = K; }

        acc = dense_gather(tab, v, lane, start, end);

        const float s = 1.0f / (float)K;
        acc.x *= s; acc.y *= s; acc.z *= s; acc.w *= s;
        op = &reinterpret_cast<float4*>(out + (size_t)node * D)[lane];
    }

    // Let the next pass launch while this grid drains its epilogue.
    cudaTriggerProgrammaticLaunchCompletion();

    if (op) {
        if (PASS > 0) {
            // out is written by the previous pass: wait for it to complete.
            cudaGridDependencySynchronize();
            red_add_f4(op, acc);       // ordered passes -> deterministic
        } else {
            cudaGridDependencySynchronize();  // no-op for the first node
            *op = acc;                 // overwrite (graph-replay safe)
        }
    }
}

extern "C" void kernel_launch(void* const* d_in, const int* in_sizes, int n_in,
                              void* d_out, int out_size)
{
    // Identify inputs by element count (robust to metadata ordering):
    // embed_table: 64,000,000 ; neigh_idx: 3,200,000 ; num_sample: 1
    long long max_sz = -1, mid_sz = -1;
    int ti = 0, ii = 1;
    for (int i = 0; i < n_in; ++i)
        if (in_sizes[i] > max_sz) { max_sz = in_sizes[i]; ti = i; }
    for (int i = 0; i < n_in; ++i)
        if (i != ti && in_sizes[i] > mid_sz) { mid_sz = in_sizes[i]; ii = i; }

    const float* tab = (const float*)d_in[ti];
    const int*   idx = (const int*)d_in[ii];
    float*       out = (float*)d_out;

    int B = out_size / D;                    // 100000
    int N = (int)(max_sz / D);               // 500000 table rows
    int chunk = (N + PASSES - 1) / PASSES;   // 166667 rows ~ 85MB

    int blocks = (B + WPB - 1) / WPB;        // 12500

    cudaLaunchAttribute attrs[1];
    attrs[0].id = cudaLaunchAttributeProgrammaticStreamSerialization;
    attrs[0].val.programmaticStreamSerializationAllowed = 1;

    cudaLaunchConfig_t cfg = {};
    cfg.gridDim  = dim3((unsigned)blocks, 1, 1);
    cfg.blockDim = dim3(WPB * 32, 1, 1);
    cfg.dynamicSmemBytes = 0;
    cfg.stream = 0;
    cfg.attrs = attrs;
    cfg.numAttrs = 1;

    cudaLaunchKernelEx(&cfg, agg_pass<0>, tab, idx, out, B, chunk, 2 * chunk);
    cudaLaunchKernelEx(&cfg, agg_pass<1>, tab, idx, out, B, chunk, 2 * chunk);
    cudaLaunchKernelEx(&cfg, agg_pass<2>, tab, idx, out, B, chunk, 2 * chunk);
}